// round 12
// baseline (speedup 1.0000x reference)
#include <cuda_runtime.h>
#include <cuda_fp16.h>
#include <cstdint>
#include <cstring>

// Problem sizes (fixed by the dataset)
#define MB   16
#define TT   512
#define NDIM 2048
#define UU   64
#define MTOT (MB*TT)   // 8192

// ----------------------------------------------------------------------------
// Scratch (__device__ globals — allocation-free per harness rules)
// A = fp16(x)              [MTOT, NDIM]
// B = fp16(Adj * wbar)     [NDIM, NDIM]
// ----------------------------------------------------------------------------
__device__ __align__(16) float g_wbar[NDIM];
__device__ float g_bmean;
__device__ __align__(16) __half g_Ah[(size_t)MTOT * NDIM];
__device__ __align__(16) __half g_Bh[(size_t)NDIM * NDIM];

// ----------------------------------------------------------------------------
// Helpers
// ----------------------------------------------------------------------------
__device__ __forceinline__ uint32_t smem_to_u32(const void* p) {
    uint32_t a;
    asm("{ .reg .u64 t; cvta.to.shared.u64 t, %1; cvt.u32.u64 %0, t; }" : "=r"(a) : "l"(p));
    return a;
}

__device__ __forceinline__ uint32_t h2_as_u32(__half2 h) {
    uint32_t u;
    memcpy(&u, &h, 4);
    return u;
}

__device__ __forceinline__ void cp16(uint32_t s, const void* g) {
    asm volatile("cp.async.cg.shared.global [%0], [%1], 16;" :: "r"(s), "l"(g));
}
__device__ __forceinline__ void cp_commit() { asm volatile("cp.async.commit_group;" ::: "memory"); }
template<int N> __device__ __forceinline__ void cp_wait() {
    asm volatile("cp.async.wait_group %0;" :: "n"(N) : "memory");
}

__device__ __forceinline__ void ldm_x4(uint32_t* r, uint32_t addr) {
    asm volatile("ldmatrix.sync.aligned.m8n8.x4.shared.b16 {%0,%1,%2,%3}, [%4];"
                 : "=r"(r[0]), "=r"(r[1]), "=r"(r[2]), "=r"(r[3]) : "r"(addr));
}

// fp16 MMA, fp32 accumulate: D += A(16x16) * B(16x8)
__device__ __forceinline__ void mma_f16(float* c, const uint32_t* a, const uint32_t* b) {
    asm volatile(
        "mma.sync.aligned.m16n8k16.row.col.f32.f16.f16.f32 "
        "{%0,%1,%2,%3}, {%4,%5,%6,%7}, {%8,%9}, {%0,%1,%2,%3};"
        : "+f"(c[0]), "+f"(c[1]), "+f"(c[2]), "+f"(c[3])
        : "r"(a[0]), "r"(a[1]), "r"(a[2]), "r"(a[3]), "r"(b[0]), "r"(b[1]));
}

// ----------------------------------------------------------------------------
// Prep: fused conv_A + wbar/bmean reduction (blocks >= NA_BLOCKS do wbar)
// ----------------------------------------------------------------------------
static constexpr int NA_BLOCKS = (int)(((size_t)MTOT * NDIM / 8) / 256);  // 8192

__global__ void conv_A_wbar_kernel(const float* __restrict__ x,
                                   const float* __restrict__ W,
                                   const float* __restrict__ bias) {
    if (blockIdx.x < NA_BLOCKS) {
        // A[m,k] = fp16(x[m,k]); 8 elems/thread
        size_t base = ((size_t)blockIdx.x * 256 + threadIdx.x) * 8;
        float4 a0 = *reinterpret_cast<const float4*>(x + base);
        float4 a1 = *reinterpret_cast<const float4*>(x + base + 4);
        uint4 o;
        o.x = h2_as_u32(__floats2half2_rn(a0.x, a0.y));
        o.y = h2_as_u32(__floats2half2_rn(a0.z, a0.w));
        o.z = h2_as_u32(__floats2half2_rn(a1.x, a1.y));
        o.w = h2_as_u32(__floats2half2_rn(a1.z, a1.w));
        *reinterpret_cast<uint4*>(reinterpret_cast<char*>(g_Ah) + base * 2) = o;
    } else {
        // wbar reduction: 32 blocks, 64 cols/block, 4-way row split
        __shared__ float part[256];
        int wb = blockIdx.x - NA_BLOCKS;     // 0..31
        int col = wb * 64 + (threadIdx.x & 63);
        int q = threadIdx.x >> 6;            // 0..3
        float s = 0.f;
        #pragma unroll
        for (int i = 0; i < UU / 4; i++) s += W[(q * (UU / 4) + i) * NDIM + col];
        part[threadIdx.x] = s;
        __syncthreads();
        if (q == 0) {
            float t = part[threadIdx.x] + part[threadIdx.x + 64] +
                      part[threadIdx.x + 128] + part[threadIdx.x + 192];
            g_wbar[col] = t * (1.0f / UU);
        }
        if (wb == 0 && threadIdx.x == 0) {
            float b = 0.f;
            for (int i = 0; i < UU; i++) b += bias[i];
            g_bmean = b * (1.0f / UU);
        }
    }
}

// B[j,k] = fp16(Adj[j,k] * wbar[k]); 8 elems/thread
__global__ void conv_B_kernel(const float* __restrict__ Adj) {
    size_t base = ((size_t)blockIdx.x * blockDim.x + threadIdx.x) * 8;
    float4 a0 = *reinterpret_cast<const float4*>(Adj + base);
    float4 a1 = *reinterpret_cast<const float4*>(Adj + base + 4);
    int k0 = (int)(base & (NDIM - 1));
    float4 w0 = *reinterpret_cast<const float4*>(g_wbar + k0);
    float4 w1 = *reinterpret_cast<const float4*>(g_wbar + k0 + 4);
    uint4 o;
    o.x = h2_as_u32(__floats2half2_rn(a0.x * w0.x, a0.y * w0.y));
    o.y = h2_as_u32(__floats2half2_rn(a0.z * w0.z, a0.w * w0.w));
    o.z = h2_as_u32(__floats2half2_rn(a1.x * w1.x, a1.y * w1.y));
    o.w = h2_as_u32(__floats2half2_rn(a1.z * w1.z, a1.w * w1.w));
    *reinterpret_cast<uint4*>(reinterpret_cast<char*>(g_Bh) + base * 2) = o;
}

// ----------------------------------------------------------------------------
// GEMM: out[m, j] = sum_k A[m,k] * B[j,k] + bmean   (fp16 in, fp32 accum)
// CTA tile 128x64, 128 threads = 4 warps (2x2), warp tile 64x32.
// KC=64 halfs (128B rows), 3-stage cp.async pipeline, 3 CTAs/SM (72KB each).
// 12 warps/SM (3/SMSP) to cover chunk-boundary sync bubbles.
// ----------------------------------------------------------------------------
static constexpr int TM = 128;
static constexpr int TN = 64;
static constexpr int KC = 64;                  // halfs per k-chunk (=128B)
static constexpr int NKC = NDIM / KC;          // 32
static constexpr int STAGES = 3;

static constexpr int A_STAGE = TM * 128;       // 16384 B
static constexpr int B_STAGE = TN * 128;       // 8192 B
static constexpr int STAGE_BYTES = A_STAGE + B_STAGE;      // 24576
static constexpr int SMEM_TOTAL = STAGES * STAGE_BYTES;    // 73728

// swizzled offset within a tile: row x 16B-chunk c (0..7)
__device__ __forceinline__ uint32_t swz(int row, int c) {
    return (uint32_t)(row * 128 + ((c ^ (row & 7)) << 4));
}

__global__ __launch_bounds__(128, 3) void gemm_kernel(float* __restrict__ out) {
    extern __shared__ char smem[];
    uint32_t sb = smem_to_u32(smem);

    const int tid = threadIdx.x;
    const int wid = tid >> 5, lid = tid & 31;
    const int wm = wid >> 1;          // 0..1  (64 rows each)
    const int wn = wid & 1;           // 0..1  (32 cols each)
    const int m0 = blockIdx.y * TM;
    const int n0 = blockIdx.x * TN;

    const char* gA = reinterpret_cast<const char*>(g_Ah + (size_t)m0 * NDIM);
    const char* gB = reinterpret_cast<const char*>(g_Bh + (size_t)n0 * NDIM);

    // 1536 granules (1024 A + 512 B), 12 per thread
    auto load_stage = [&](int kc, int stage) {
        uint32_t abase = sb + stage * STAGE_BYTES;
        uint32_t bbase = abase + A_STAGE;
        size_t koff = (size_t)kc * KC * 2;     // bytes along k (fp16)
        #pragma unroll
        for (int j = 0; j < 12; j++) {
            int gi = tid + j * 128;
            int c = gi & 7;
            if (gi < 1024) {
                int r = gi >> 3;               // 0..127
                cp16(abase + swz(r, c), gA + (size_t)r * (NDIM * 2) + koff + c * 16);
            } else {
                int r = (gi - 1024) >> 3;      // 0..63
                cp16(bbase + swz(r, c), gB + (size_t)r * (NDIM * 2) + koff + c * 16);
            }
        }
    };

    // ldmatrix per-thread roles (canonical b16 x4 patterns)
    const int aRowOff = (lid & 15);
    const int aCsel = lid >> 4;
    const int bRowOff = (lid & 7) + ((lid >> 4) << 3);
    const int bCsel = (lid >> 3) & 1;

    float acc[4][4][4];
    #pragma unroll
    for (int i = 0; i < 4; i++)
        #pragma unroll
        for (int j = 0; j < 4; j++)
            #pragma unroll
            for (int q = 0; q < 4; q++) acc[i][j][q] = 0.f;

    #pragma unroll
    for (int s = 0; s < STAGES - 1; s++) { load_stage(s, s); cp_commit(); }

    int stage = 0;
    for (int i = 0; i < NKC; i++) {
        cp_wait<STAGES - 2>();
        __syncthreads();

        uint32_t abase = sb + stage * STAGE_BYTES;
        uint32_t bbase = abase + A_STAGE;

        #pragma unroll
        for (int ks = 0; ks < KC / 16; ks++) {   // 4 k16 steps
            uint32_t aR[4][4], bR[2][4];
            #pragma unroll
            for (int mb = 0; mb < 4; mb++) {
                int row = wm * 64 + mb * 16 + aRowOff;
                ldm_x4(aR[mb], abase + swz(row, ks * 2 + aCsel));
            }
            #pragma unroll
            for (int bp = 0; bp < 2; bp++) {
                int row = wn * 32 + bp * 16 + bRowOff;
                ldm_x4(bR[bp], bbase + swz(row, ks * 2 + bCsel));
            }

            if (ks == 0) {
                int nxt = i + STAGES - 1;
                if (nxt < NKC) {
                    int nstage = stage + (STAGES - 1);
                    if (nstage >= STAGES) nstage -= STAGES;
                    load_stage(nxt, nstage);
                }
                cp_commit();
            }

            #pragma unroll
            for (int mb = 0; mb < 4; mb++) {
                #pragma unroll
                for (int nb = 0; nb < 4; nb++) {
                    mma_f16(acc[mb][nb], aR[mb], &bR[nb >> 1][(nb & 1) * 2]);
                }
            }
        }

        stage++;
        if (stage == STAGES) stage = 0;
    }

    // Epilogue: each warp writes its 64x32 block
    float bm = g_bmean;
    #pragma unroll
    for (int mb = 0; mb < 4; mb++) {
        int row = m0 + wm * 64 + mb * 16 + (lid >> 2);
        #pragma unroll
        for (int nb = 0; nb < 4; nb++) {
            int col = n0 + wn * 32 + nb * 8 + (lid & 3) * 2;
            float2 v0, v1;
            v0.x = acc[mb][nb][0] + bm;
            v0.y = acc[mb][nb][1] + bm;
            v1.x = acc[mb][nb][2] + bm;
            v1.y = acc[mb][nb][3] + bm;
            *reinterpret_cast<float2*>(out + (size_t)row * NDIM + col) = v0;
            *reinterpret_cast<float2*>(out + (size_t)(row + 8) * NDIM + col) = v1;
        }
    }
}

// ----------------------------------------------------------------------------
// Launch
// ----------------------------------------------------------------------------
extern "C" void kernel_launch(void* const* d_in, const int* in_sizes, int n_in,
                              void* d_out, int out_size) {
    const float* x    = (const float*)d_in[0];   // [16, 512, 2048]
    const float* Adj  = (const float*)d_in[1];   // [2048, 2048]
    const float* W    = (const float*)d_in[2];   // [64, 2048]
    const float* bias = (const float*)d_in[3];   // [64]
    float* out = (float*)d_out;                  // [16, 512, 2048]

    conv_A_wbar_kernel<<<NA_BLOCKS + 32, 256>>>(x, W, bias);
    conv_B_kernel<<<(NDIM * NDIM / 8) / 256, 256>>>(Adj);

    cudaFuncSetAttribute(gemm_kernel, cudaFuncAttributeMaxDynamicSharedMemorySize, SMEM_TOTAL);
    gemm_kernel<<<dim3(NDIM / TN, MTOT / TM), 128, SMEM_TOTAL>>>(out);
}

// round 13
// speedup vs baseline: 1.0726x; 1.0726x over previous
#include <cuda_runtime.h>
#include <cuda_fp16.h>
#include <cstdint>
#include <cstring>

// Problem sizes (fixed by the dataset)
#define MB   16
#define TT   512
#define NDIM 2048
#define UU   64
#define MTOT (MB*TT)   // 8192

// ----------------------------------------------------------------------------
// Scratch (__device__ globals — allocation-free per harness rules)
// A = fp16(x)              [MTOT, NDIM]
// B = fp16(Adj * wbar)     [NDIM, NDIM]
// ----------------------------------------------------------------------------
__device__ __align__(16) float g_wbar[NDIM];
__device__ float g_bmean;
__device__ __align__(16) __half g_Ah[(size_t)MTOT * NDIM];
__device__ __align__(16) __half g_Bh[(size_t)NDIM * NDIM];

// ----------------------------------------------------------------------------
// Helpers
// ----------------------------------------------------------------------------
__device__ __forceinline__ uint32_t smem_to_u32(const void* p) {
    uint32_t a;
    asm("{ .reg .u64 t; cvta.to.shared.u64 t, %1; cvt.u32.u64 %0, t; }" : "=r"(a) : "l"(p));
    return a;
}

__device__ __forceinline__ uint32_t h2_as_u32(__half2 h) {
    uint32_t u;
    memcpy(&u, &h, 4);
    return u;
}

__device__ __forceinline__ void cp16(uint32_t s, const void* g) {
    asm volatile("cp.async.cg.shared.global [%0], [%1], 16;" :: "r"(s), "l"(g));
}
__device__ __forceinline__ void cp_commit() { asm volatile("cp.async.commit_group;" ::: "memory"); }
template<int N> __device__ __forceinline__ void cp_wait() {
    asm volatile("cp.async.wait_group %0;" :: "n"(N) : "memory");
}

__device__ __forceinline__ void ldm_x4(uint32_t* r, uint32_t addr) {
    asm volatile("ldmatrix.sync.aligned.m8n8.x4.shared.b16 {%0,%1,%2,%3}, [%4];"
                 : "=r"(r[0]), "=r"(r[1]), "=r"(r[2]), "=r"(r[3]) : "r"(addr));
}

// fp16 MMA, fp32 accumulate: D += A(16x16) * B(16x8)
__device__ __forceinline__ void mma_f16(float* c, const uint32_t* a, const uint32_t* b) {
    asm volatile(
        "mma.sync.aligned.m16n8k16.row.col.f32.f16.f16.f32 "
        "{%0,%1,%2,%3}, {%4,%5,%6,%7}, {%8,%9}, {%0,%1,%2,%3};"
        : "+f"(c[0]), "+f"(c[1]), "+f"(c[2]), "+f"(c[3])
        : "r"(a[0]), "r"(a[1]), "r"(a[2]), "r"(a[3]), "r"(b[0]), "r"(b[1]));
}

// ----------------------------------------------------------------------------
// Prep 1: wbar + bmean only (tiny, fast)
// ----------------------------------------------------------------------------
__global__ void wbar_kernel(const float* __restrict__ W, const float* __restrict__ bias) {
    __shared__ float part[256];
    int col = blockIdx.x * 64 + (threadIdx.x & 63);
    int q = threadIdx.x >> 6;            // 0..3
    float s = 0.f;
    #pragma unroll
    for (int i = 0; i < UU / 4; i++) s += W[(q * (UU / 4) + i) * NDIM + col];
    part[threadIdx.x] = s;
    __syncthreads();
    if (q == 0) {
        float t = part[threadIdx.x] + part[threadIdx.x + 64] +
                  part[threadIdx.x + 128] + part[threadIdx.x + 192];
        g_wbar[col] = t * (1.0f / UU);
    }
    if (blockIdx.x == 0 && threadIdx.x == 0) {
        float b = 0.f;
        for (int i = 0; i < UU; i++) b += bias[i];
        g_bmean = b * (1.0f / UU);
    }
}

// ----------------------------------------------------------------------------
// Prep 2: fused A + B conversion in one launch.
// A blocks: 16 elems/thread (4 float4 loads -> MLP 4). NA16_BLOCKS = 4096.
// B blocks: 8 elems/thread. NB_BLOCKS = 2048.
// ----------------------------------------------------------------------------
static constexpr int NA16_BLOCKS = (int)(((size_t)MTOT * NDIM / 16) / 256);  // 4096
static constexpr int NB_BLOCKS   = (NDIM * NDIM / 8) / 256;                  // 2048

__global__ void conv_AB_kernel(const float* __restrict__ x, const float* __restrict__ Adj) {
    if (blockIdx.x < NA16_BLOCKS) {
        // A[m,k] = fp16(x[m,k]); 16 elems/thread
        size_t base = ((size_t)blockIdx.x * 256 + threadIdx.x) * 16;
        float4 a0 = *reinterpret_cast<const float4*>(x + base);
        float4 a1 = *reinterpret_cast<const float4*>(x + base + 4);
        float4 a2 = *reinterpret_cast<const float4*>(x + base + 8);
        float4 a3 = *reinterpret_cast<const float4*>(x + base + 12);
        uint4 o0, o1;
        o0.x = h2_as_u32(__floats2half2_rn(a0.x, a0.y));
        o0.y = h2_as_u32(__floats2half2_rn(a0.z, a0.w));
        o0.z = h2_as_u32(__floats2half2_rn(a1.x, a1.y));
        o0.w = h2_as_u32(__floats2half2_rn(a1.z, a1.w));
        o1.x = h2_as_u32(__floats2half2_rn(a2.x, a2.y));
        o1.y = h2_as_u32(__floats2half2_rn(a2.z, a2.w));
        o1.z = h2_as_u32(__floats2half2_rn(a3.x, a3.y));
        o1.w = h2_as_u32(__floats2half2_rn(a3.z, a3.w));
        *reinterpret_cast<uint4*>(reinterpret_cast<char*>(g_Ah) + base * 2) = o0;
        *reinterpret_cast<uint4*>(reinterpret_cast<char*>(g_Ah) + base * 2 + 16) = o1;
    } else {
        // B[j,k] = fp16(Adj[j,k] * wbar[k]); 8 elems/thread
        size_t base = ((size_t)(blockIdx.x - NA16_BLOCKS) * 256 + threadIdx.x) * 8;
        float4 a0 = *reinterpret_cast<const float4*>(Adj + base);
        float4 a1 = *reinterpret_cast<const float4*>(Adj + base + 4);
        int k0 = (int)(base & (NDIM - 1));
        float4 w0 = *reinterpret_cast<const float4*>(g_wbar + k0);
        float4 w1 = *reinterpret_cast<const float4*>(g_wbar + k0 + 4);
        uint4 o;
        o.x = h2_as_u32(__floats2half2_rn(a0.x * w0.x, a0.y * w0.y));
        o.y = h2_as_u32(__floats2half2_rn(a0.z * w0.z, a0.w * w0.w));
        o.z = h2_as_u32(__floats2half2_rn(a1.x * w1.x, a1.y * w1.y));
        o.w = h2_as_u32(__floats2half2_rn(a1.z * w1.z, a1.w * w1.w));
        *reinterpret_cast<uint4*>(reinterpret_cast<char*>(g_Bh) + base * 2) = o;
    }
}

// ----------------------------------------------------------------------------
// GEMM: out[m, j] = sum_k A[m,k] * B[j,k] + bmean   (fp16 in, fp32 accum)
// CTA tile 128x128, 128 threads = 4 warps (2x2), warp tile 64x64.
// KC=64 halfs (128B rows), 3-stage cp.async pipeline, 2 CTAs/SM.
// (identical to the round-8 best GEMM)
// ----------------------------------------------------------------------------
static constexpr int TM = 128;
static constexpr int TN = 128;
static constexpr int KC = 64;                  // halfs per k-chunk (=128B)
static constexpr int NKC = NDIM / KC;          // 32
static constexpr int STAGES = 3;

static constexpr int A_STAGE = TM * 128;       // 16384 B
static constexpr int B_STAGE = TN * 128;       // 16384 B
static constexpr int STAGE_BYTES = A_STAGE + B_STAGE;      // 32768
static constexpr int SMEM_TOTAL = STAGES * STAGE_BYTES;    // 98304

// swizzled offset within a tile: row (0..127) x 16B-chunk c (0..7)
__device__ __forceinline__ uint32_t swz(int row, int c) {
    return (uint32_t)(row * 128 + ((c ^ (row & 7)) << 4));
}

__global__ __launch_bounds__(128, 2) void gemm_kernel(float* __restrict__ out) {
    extern __shared__ char smem[];
    uint32_t sb = smem_to_u32(smem);

    const int tid = threadIdx.x;
    const int wid = tid >> 5, lid = tid & 31;
    const int wm = wid >> 1;          // 0..1  (64 rows each)
    const int wn = wid & 1;           // 0..1  (64 cols each)
    const int m0 = blockIdx.y * TM;
    const int n0 = blockIdx.x * TN;

    const char* gA = reinterpret_cast<const char*>(g_Ah + (size_t)m0 * NDIM);
    const char* gB = reinterpret_cast<const char*>(g_Bh + (size_t)n0 * NDIM);

    // 2048 granules (1024 A + 1024 B), 16 per thread
    auto load_stage = [&](int kc, int stage) {
        uint32_t abase = sb + stage * STAGE_BYTES;
        uint32_t bbase = abase + A_STAGE;
        size_t koff = (size_t)kc * KC * 2;     // bytes along k (fp16)
        #pragma unroll
        for (int j = 0; j < 16; j++) {
            int gi = tid + j * 128;
            int r = (gi >> 3) & 127, c = gi & 7;
            if (gi < 1024) {
                cp16(abase + swz(r, c), gA + (size_t)r * (NDIM * 2) + koff + c * 16);
            } else {
                cp16(bbase + swz(r, c), gB + (size_t)r * (NDIM * 2) + koff + c * 16);
            }
        }
    };

    // ldmatrix per-thread roles (canonical b16 x4 patterns)
    const int aRowOff = (lid & 15);
    const int aCsel = lid >> 4;
    const int bRowOff = (lid & 7) + ((lid >> 4) << 3);
    const int bCsel = (lid >> 3) & 1;

    float acc[4][8][4];
    #pragma unroll
    for (int i = 0; i < 4; i++)
        #pragma unroll
        for (int j = 0; j < 8; j++)
            #pragma unroll
            for (int q = 0; q < 4; q++) acc[i][j][q] = 0.f;

    #pragma unroll
    for (int s = 0; s < STAGES - 1; s++) { load_stage(s, s); cp_commit(); }

    int stage = 0;
    for (int i = 0; i < NKC; i++) {
        cp_wait<STAGES - 2>();
        __syncthreads();

        uint32_t abase = sb + stage * STAGE_BYTES;
        uint32_t bbase = abase + A_STAGE;

        #pragma unroll
        for (int ks = 0; ks < KC / 16; ks++) {   // 4 k16 steps
            uint32_t aR[4][4], bR[4][4];
            #pragma unroll
            for (int mb = 0; mb < 4; mb++) {
                int row = wm * 64 + mb * 16 + aRowOff;
                ldm_x4(aR[mb], abase + swz(row, ks * 2 + aCsel));
            }
            #pragma unroll
            for (int bp = 0; bp < 4; bp++) {
                int row = wn * 64 + bp * 16 + bRowOff;
                ldm_x4(bR[bp], bbase + swz(row, ks * 2 + bCsel));
            }

            if (ks == 0) {
                int nxt = i + STAGES - 1;
                if (nxt < NKC) {
                    int nstage = stage + (STAGES - 1);
                    if (nstage >= STAGES) nstage -= STAGES;
                    load_stage(nxt, nstage);
                }
                cp_commit();
            }

            #pragma unroll
            for (int mb = 0; mb < 4; mb++) {
                #pragma unroll
                for (int nb = 0; nb < 8; nb++) {
                    mma_f16(acc[mb][nb], aR[mb], &bR[nb >> 1][(nb & 1) * 2]);
                }
            }
        }

        stage++;
        if (stage == STAGES) stage = 0;
    }

    // Epilogue: each warp writes its 64x64 block
    float bm = g_bmean;
    #pragma unroll
    for (int mb = 0; mb < 4; mb++) {
        int row = m0 + wm * 64 + mb * 16 + (lid >> 2);
        #pragma unroll
        for (int nb = 0; nb < 8; nb++) {
            int col = n0 + wn * 64 + nb * 8 + (lid & 3) * 2;
            float2 v0, v1;
            v0.x = acc[mb][nb][0] + bm;
            v0.y = acc[mb][nb][1] + bm;
            v1.x = acc[mb][nb][2] + bm;
            v1.y = acc[mb][nb][3] + bm;
            *reinterpret_cast<float2*>(out + (size_t)row * NDIM + col) = v0;
            *reinterpret_cast<float2*>(out + (size_t)(row + 8) * NDIM + col) = v1;
        }
    }
}

// ----------------------------------------------------------------------------
// Launch
// ----------------------------------------------------------------------------
extern "C" void kernel_launch(void* const* d_in, const int* in_sizes, int n_in,
                              void* d_out, int out_size) {
    const float* x    = (const float*)d_in[0];   // [16, 512, 2048]
    const float* Adj  = (const float*)d_in[1];   // [2048, 2048]
    const float* W    = (const float*)d_in[2];   // [64, 2048]
    const float* bias = (const float*)d_in[3];   // [64]
    float* out = (float*)d_out;                  // [16, 512, 2048]

    wbar_kernel<<<32, 256>>>(W, bias);
    conv_AB_kernel<<<NA16_BLOCKS + NB_BLOCKS, 256>>>(x, Adj);

    cudaFuncSetAttribute(gemm_kernel, cudaFuncAttributeMaxDynamicSharedMemorySize, SMEM_TOTAL);
    gemm_kernel<<<dim3(NDIM / TN, MTOT / TM), 128, SMEM_TOTAL>>>(out);
}